// round 7
// baseline (speedup 1.0000x reference)
#include <cuda_runtime.h>
#include <cuda_bf16.h>
#include <cstdint>
#include <cstddef>

#define BB 8
#define LL 2048
#define DM 1024
#define HH 120
#define HP 128
#define MTOT (BB*LL)
#define LOG2E 1.4426950408889634f

// ---------------------------------------------------------------------------
// Scratch (__device__ globals: allocation-free per harness rules)
// ---------------------------------------------------------------------------
__device__ __align__(16) float g_bc[HP];
__device__ __align__(16) float g_norm[MTOT];
__device__ __align__(16) __nv_bfloat16 g_WtH[HP * DM];
__device__ __align__(16) __nv_bfloat16 g_WtL[HP * DM];
__device__ __align__(16) __nv_bfloat16 g_uh[(size_t)MTOT * HP];
__device__ __align__(16) __nv_bfloat16 g_ul[(size_t)MTOT * HP];

// ---------------------------------------------------------------------------
// Helpers
// ---------------------------------------------------------------------------
__device__ __forceinline__ uint32_t smem_u32(const void* p) {
    uint32_t a;
    asm("{ .reg .u64 t; cvta.to.shared.u64 t, %1; cvt.u32.u64 %0, t; }" : "=r"(a) : "l"(p));
    return a;
}
__device__ __forceinline__ void ldsm4(uint32_t (&r)[4], uint32_t addr) {
    asm volatile("ldmatrix.sync.aligned.m8n8.x4.shared.b16 {%0,%1,%2,%3}, [%4];"
        : "=r"(r[0]), "=r"(r[1]), "=r"(r[2]), "=r"(r[3]) : "r"(addr));
}
__device__ __forceinline__ void hmma(float (&c)[4], const uint32_t (&a)[4],
                                     uint32_t b0, uint32_t b1) {
    asm volatile("mma.sync.aligned.m16n8k16.row.col.f32.bf16.bf16.f32 "
        "{%0,%1,%2,%3}, {%4,%5,%6,%7}, {%8,%9}, {%0,%1,%2,%3};"
        : "+f"(c[0]), "+f"(c[1]), "+f"(c[2]), "+f"(c[3])
        : "r"(a[0]), "r"(a[1]), "r"(a[2]), "r"(a[3]), "r"(b0), "r"(b1));
}
__device__ __forceinline__ void cpa16(uint32_t dst, const void* src) {
    asm volatile("cp.async.cg.shared.global [%0], [%1], 16;" :: "r"(dst), "l"(src));
}
#define CP_COMMIT() asm volatile("cp.async.commit_group;" ::: "memory")
#define CP_WAIT0()  asm volatile("cp.async.wait_group 0;" ::: "memory")

__device__ __forceinline__ float ex2(float x) {
    float r; asm("ex2.approx.ftz.f32 %0, %1;" : "=f"(r) : "f"(x)); return r;
}
__device__ __forceinline__ void split_store(__nv_bfloat16* H, __nv_bfloat16* L,
                                            size_t idx, float x, float y) {
    __nv_bfloat162 h = __floats2bfloat162_rn(x, y);
    float hx = __bfloat162float(h.x), hy = __bfloat162float(h.y);
    __nv_bfloat162 lo = __floats2bfloat162_rn(x - hx, y - hy);
    *(__nv_bfloat162*)(H + idx) = h;
    *(__nv_bfloat162*)(L + idx) = lo;
}

// TN mma over one k-chunk. A,B smem row-major [rows][k], stride STRB bytes.
// Warp tile 32(m) x 32(n). KS ksteps of k=16.
template<int STRB, int KS>
__device__ __forceinline__ void mma32(uint32_t aBase, uint32_t bBase,
                                      float (&acc)[2][4][4],
                                      int lid, int m0w, int n0) {
    uint32_t aA = aBase + (uint32_t)(m0w + (lid & 15)) * STRB + (uint32_t)((lid >> 4) * 16);
    uint32_t bA = bBase + (uint32_t)(n0 + (lid & 7) + ((lid >> 4) & 1) * 8) * STRB
                + (uint32_t)(((lid >> 3) & 1) * 16);
    #pragma unroll
    for (int ks = 0; ks < KS; ++ks) {
        uint32_t kb = (uint32_t)ks * 32;
        uint32_t afr[2][4];
        #pragma unroll
        for (int mt = 0; mt < 2; ++mt) ldsm4(afr[mt], aA + mt * 16 * STRB + kb);
        uint32_t bfr[2][4];
        #pragma unroll
        for (int g = 0; g < 2; ++g)    ldsm4(bfr[g], bA + g * 16 * STRB + kb);
        #pragma unroll
        for (int mt = 0; mt < 2; ++mt)
            #pragma unroll
            for (int nt = 0; nt < 4; ++nt)
                hmma(acc[mt][nt], afr[mt],
                     bfr[nt >> 1][(nt & 1) * 2], bfr[nt >> 1][(nt & 1) * 2 + 1]);
    }
}

// ---------------------------------------------------------------------------
// K1: Wc^T (bf16 hi/lo)
// ---------------------------------------------------------------------------
__global__ __launch_bounds__(256) void k_prep(const float* __restrict__ qw,
                                              const float* __restrict__ w) {
    __shared__ float Aq[8][64];
    __shared__ float Ww[8][128];
    int tid = threadIdx.x;
    int ty = tid >> 4, tx = tid & 15;
    int d0 = blockIdx.x * 64;

    float acc[4][8];
    #pragma unroll
    for (int r = 0; r < 4; ++r)
        #pragma unroll
        for (int c = 0; c < 8; ++c) acc[r][c] = 0.f;

    for (int kk = 0; kk < HH; kk += 8) {
        {
            int i = tid >> 5, j = (tid & 31) * 2;
            const float* s = &qw[(size_t)(kk + i) * DM + d0 + j];
            Aq[i][j] = s[0]; Aq[i][j + 1] = s[1];
        }
        {
            int i = tid >> 5, c = (tid & 31) * 4;
            #pragma unroll
            for (int q2 = 0; q2 < 4; ++q2) {
                int h = c + q2;
                Ww[i][h] = (h < HH) ? w[(size_t)(kk + i) * HH + h] : 0.f;
            }
        }
        __syncthreads();
        #pragma unroll
        for (int k = 0; k < 8; ++k) {
            float a[4], b[8];
            #pragma unroll
            for (int r = 0; r < 4; ++r) a[r] = Aq[k][ty * 4 + r];
            *(float4*)&b[0] = *(const float4*)&Ww[k][tx * 8];
            *(float4*)&b[4] = *(const float4*)&Ww[k][tx * 8 + 4];
            #pragma unroll
            for (int r = 0; r < 4; ++r)
                #pragma unroll
                for (int c = 0; c < 8; ++c) acc[r][c] += a[r] * b[c];
        }
        __syncthreads();
    }
    #pragma unroll
    for (int r = 0; r < 4; ++r)
        #pragma unroll
        for (int c = 0; c < 8; ++c) {
            int h = tx * 8 + c, d = d0 + ty * 4 + r;
            float v = acc[r][c];
            __nv_bfloat16 hb = __float2bfloat16(v);
            g_WtH[(size_t)h * DM + d] = hb;
            g_WtL[(size_t)h * DM + d] = __float2bfloat16(v - __bfloat162float(hb));
        }
}

__global__ void k_bias(const float* __restrict__ qb, const float* __restrict__ w) {
    int h = threadIdx.x;
    float b = 0.f;
    if (h < HH) {
        #pragma unroll 4
        for (int p = 0; p < HH; ++p) b += qb[p] * w[p * HH + h];
    }
    g_bc[h] = b;
}

// ---------------------------------------------------------------------------
// K2: u = query @ Wc + bc via bf16 split-3 HMMA. 512 thr, warp grid 4x4.
// ---------------------------------------------------------------------------
#define P_AH 0
#define P_AL 18432
#define P_BH 36864
#define P_BL 55296
#define P_BC 73728
#define P_RED 74240
#define P_TOTAL 76288
#define STR2 144

extern __shared__ char smem_dyn[];

__global__ __launch_bounds__(512, 1) void k_proj(const float* __restrict__ q) {
    char* sm = smem_dyn;
    uint32_t sb = smem_u32(sm);
    int tid = threadIdx.x;
    int wid = tid >> 5, lid = tid & 31;
    int m0w = (wid & 3) * 32;
    int nw = wid >> 2;
    int n0 = nw * 32;
    int m0g = blockIdx.x * 128;

    float* bc_s = (float*)(sm + P_BC);
    float* red = (float*)(sm + P_RED);         // 4 x 128 floats
    if (tid < 128) bc_s[tid] = g_bc[tid];

    float acc[2][4][4];
    #pragma unroll
    for (int mt = 0; mt < 2; ++mt)
        #pragma unroll
        for (int nt = 0; nt < 4; ++nt)
            #pragma unroll
            for (int i = 0; i < 4; ++i) acc[mt][nt][i] = 0.f;

    float4 qr[4];
    #pragma unroll
    for (int l = 0; l < 4; ++l) {
        int i = tid + 512 * l, r = i >> 4, c4 = (i & 15) * 4;
        qr[l] = *(const float4*)&q[(size_t)(m0g + r) * DM + c4];
    }

    for (int kbi = 0; kbi < 16; ++kbi) {
        int kb = kbi * 64;
        #pragma unroll
        for (int l = 0; l < 2; ++l) {
            int i = tid + 512 * l, r = i >> 3, sg = i & 7;
            uint32_t doff = (uint32_t)r * STR2 + sg * 16;
            size_t soff = (size_t)r * (DM * 2) + (size_t)kb * 2 + sg * 16;
            cpa16(sb + P_BH + doff, (const char*)g_WtH + soff);
            cpa16(sb + P_BL + doff, (const char*)g_WtL + soff);
        }
        CP_COMMIT();
        #pragma unroll
        for (int l = 0; l < 4; ++l) {
            int i = tid + 512 * l, r = i >> 4, c4 = (i & 15) * 4;
            float4 v = qr[l];
            __nv_bfloat162 h01 = __floats2bfloat162_rn(v.x, v.y);
            __nv_bfloat162 h23 = __floats2bfloat162_rn(v.z, v.w);
            __nv_bfloat162 l01 = __floats2bfloat162_rn(v.x - __bfloat162float(h01.x),
                                                       v.y - __bfloat162float(h01.y));
            __nv_bfloat162 l23 = __floats2bfloat162_rn(v.z - __bfloat162float(h23.x),
                                                       v.w - __bfloat162float(h23.y));
            char* d = sm + P_AH + r * STR2 + c4 * 2;
            ((__nv_bfloat162*)d)[0] = h01; ((__nv_bfloat162*)d)[1] = h23;
            char* d2 = sm + P_AL + r * STR2 + c4 * 2;
            ((__nv_bfloat162*)d2)[0] = l01; ((__nv_bfloat162*)d2)[1] = l23;
        }
        if (kbi < 15) {
            #pragma unroll
            for (int l = 0; l < 4; ++l) {
                int i = tid + 512 * l, r = i >> 4, c4 = (i & 15) * 4;
                qr[l] = *(const float4*)&q[(size_t)(m0g + r) * DM + kb + 64 + c4];
            }
        }
        CP_WAIT0();
        __syncthreads();
        mma32<STR2, 4>(sb + P_AH, sb + P_BH, acc, lid, m0w, n0);
        mma32<STR2, 4>(sb + P_AH, sb + P_BL, acc, lid, m0w, n0);
        mma32<STR2, 4>(sb + P_AL, sb + P_BH, acc, lid, m0w, n0);
        __syncthreads();
    }

    // Epilogue: bias, norms, bf16 split store
    float sums[2][2] = {{0.f, 0.f}, {0.f, 0.f}};
    #pragma unroll
    for (int mt = 0; mt < 2; ++mt)
        #pragma unroll
        for (int nt = 0; nt < 4; ++nt) {
            int col = n0 + nt * 8 + (lid & 3) * 2;
            float b0 = bc_s[col], b1 = bc_s[col + 1];
            int r1 = m0w + mt * 16 + (lid >> 2);
            float u00 = acc[mt][nt][0] + b0, u01 = acc[mt][nt][1] + b1;
            float u10 = acc[mt][nt][2] + b0, u11 = acc[mt][nt][3] + b1;
            sums[mt][0] += u00 * u00 + u01 * u01;
            sums[mt][1] += u10 * u10 + u11 * u11;
            split_store(g_uh, g_ul, (size_t)(m0g + r1) * HP + col, u00, u01);
            split_store(g_uh, g_ul, (size_t)(m0g + r1 + 8) * HP + col, u10, u11);
        }
    #pragma unroll
    for (int mt = 0; mt < 2; ++mt)
        #pragma unroll
        for (int hf = 0; hf < 2; ++hf) {
            float s = sums[mt][hf];
            s += __shfl_xor_sync(0xFFFFFFFF, s, 1);
            s += __shfl_xor_sync(0xFFFFFFFF, s, 2);
            if ((lid & 3) == 0)
                red[nw * 128 + m0w + mt * 16 + (lid >> 2) + hf * 8] = s;
        }
    __syncthreads();
    if (tid < 128)
        g_norm[m0g + tid] = (red[tid] + red[128 + tid]) + (red[256 + tid] + red[384 + tid]);
}

// ---------------------------------------------------------------------------
// K3: scores. 512 thr, warp grid 4x4 (32x32 warp tiles), 16 j-tiles.
// ---------------------------------------------------------------------------
#define A_H    0
#define A_L    34816
#define B0_H   69632
#define B1_H   139264
#define S_NJ   208896
#define S_NI   217088
#define S_RED  217600
#define S_RINV 218112
#define S_TOT  218624
#define STR3   272
#define BTILE  34816

__device__ __forceinline__ void k3_cp_tile(uint32_t dstH, uint32_t dstL,
                                           int row0, int tid) {
    #pragma unroll
    for (int l = 0; l < 4; ++l) {
        int i = tid + 512 * l, r = i >> 4, c = i & 15;
        uint32_t doff = (uint32_t)r * STR3 + c * 16;
        size_t soff = (size_t)(row0 + r) * (HP * 2) + c * 16;
        cpa16(dstH + doff, (const char*)g_uh + soff);
        cpa16(dstL + doff, (const char*)g_ul + soff);
    }
}

__global__ __launch_bounds__(512, 1) void k_attn(const float* __restrict__ pid,
                                                 float* __restrict__ out) {
    char* sm = smem_dyn;
    uint32_t sb = smem_u32(sm);
    int tid = threadIdx.x;
    int wid = tid >> 5, lid = tid & 31;
    int m0w = (wid & 3) * 32;
    int n0 = (wid >> 2) * 32;

    int b = blockIdx.y;
    int stripe = blockIdx.x;
    int i0 = b * LL + stripe * 128;

    float scale = pid[0] * pid[0];
    float c1 = -0.5f * scale * LOG2E;

    float* nj_s = (float*)(sm + S_NJ);
    float* ni_s = (float*)(sm + S_NI);
    float* red = (float*)(sm + S_RED);
    float* rinv_s = (float*)(sm + S_RINV);

    {
        float4* njd = (float4*)nj_s;
        const float4* njs = (const float4*)&g_norm[b * LL];
        njd[tid] = njs[tid];                   // 512 float4 = 2048 floats
        if (tid < 128) ni_s[tid] = g_norm[i0 + tid];
    }
    k3_cp_tile(sb + A_H, sb + A_L, i0, tid);
    k3_cp_tile(sb + B0_H, sb + B0_H + BTILE, b * LL, tid);
    CP_COMMIT();
    CP_WAIT0();
    __syncthreads();

    float rs[8];
    #pragma unroll
    for (int r = 0; r < 8; ++r) rs[r] = 0.f;

    for (int jt = 0; jt < 16; ++jt) {
        int buf = jt & 1;
        uint32_t bH = sb + (buf ? B1_H : B0_H);
        uint32_t bL = bH + BTILE;
        if (jt < 15) {
            uint32_t nH = sb + ((buf ^ 1) ? B1_H : B0_H);
            k3_cp_tile(nH, nH + BTILE, b * LL + (jt + 1) * 128, tid);
            CP_COMMIT();
        }

        float acc[2][4][4];
        #pragma unroll
        for (int mt = 0; mt < 2; ++mt)
            #pragma unroll
            for (int nt = 0; nt < 4; ++nt)
                #pragma unroll
                for (int i = 0; i < 4; ++i) acc[mt][nt][i] = 0.f;

        mma32<STR3, 8>(sb + A_H, bH, acc, lid, m0w, n0);
        mma32<STR3, 8>(sb + A_H, bL, acc, lid, m0w, n0);
        mma32<STR3, 8>(sb + A_L, bH, acc, lid, m0w, n0);
        __syncthreads();   // all ldmatrix reads of B(buf) done

        // stage acc (fp32) into consumed B buffer: [128][132] floats
        float* stg = (float*)(sm + (buf ? B1_H : B0_H));
        #pragma unroll
        for (int mt = 0; mt < 2; ++mt)
            #pragma unroll
            for (int nt = 0; nt < 4; ++nt) {
                int row = m0w + mt * 16 + (lid >> 2);
                int col = n0 + nt * 8 + (lid & 3) * 2;
                *(float2*)&stg[row * 132 + col] = make_float2(acc[mt][nt][0], acc[mt][nt][1]);
                *(float2*)&stg[(row + 8) * 132 + col] = make_float2(acc[mt][nt][2], acc[mt][nt][3]);
            }
        __syncthreads();

        // epilogue: warp w owns rows w*8..+7; coalesced 512B/warp stores
        #pragma unroll
        for (int rr = 0; rr < 8; ++rr) {
            int row = wid * 8 + rr;
            float nir = ni_s[row];
            float4 S4 = *(float4*)&stg[row * 132 + lid * 4];
            float4 nj4 = *(const float4*)&nj_s[jt * 128 + lid * 4];
            float e0 = ex2(LOG2E * ex2(c1 * (nir + nj4.x - 2.f * S4.x)));
            float e1 = ex2(LOG2E * ex2(c1 * (nir + nj4.y - 2.f * S4.y)));
            float e2 = ex2(LOG2E * ex2(c1 * (nir + nj4.z - 2.f * S4.z)));
            float e3 = ex2(LOG2E * ex2(c1 * (nir + nj4.w - 2.f * S4.w)));
            float p = (e0 + e1) + (e2 + e3);
            p += __shfl_xor_sync(0xFFFFFFFF, p, 16);
            p += __shfl_xor_sync(0xFFFFFFFF, p, 8);
            p += __shfl_xor_sync(0xFFFFFFFF, p, 4);
            p += __shfl_xor_sync(0xFFFFFFFF, p, 2);
            p += __shfl_xor_sync(0xFFFFFFFF, p, 1);
            rs[rr] += p;
            size_t o = (size_t)(i0 + row) * LL + jt * 128 + lid * 4;
            *(float4*)&out[o] = make_float4(e0, e1, e2, e3);
        }
        CP_WAIT0();
        __syncthreads();
    }

    if (lid == 0) {
        #pragma unroll
        for (int rr = 0; rr < 8; ++rr) red[wid * 8 + rr] = rs[rr];
    }
    __syncthreads();
    if (tid < 128) rinv_s[tid] = 1.0f / red[tid];
    __syncthreads();

    // normalize pass (coalesced)
    #pragma unroll 1
    for (int rr = 0; rr < 8; ++rr) {
        int row = wid * 8 + rr;
        float sc = rinv_s[row];
        float* rp = &out[(size_t)(i0 + row) * LL];
        #pragma unroll 4
        for (int seg = 0; seg < 16; ++seg) {
            int idx = seg * 128 + lid * 4;
            float4 v = *(float4*)&rp[idx];
            v.x *= sc; v.y *= sc; v.z *= sc; v.w *= sc;
            *(float4*)&rp[idx] = v;
        }
    }
}

// ---------------------------------------------------------------------------
extern "C" void kernel_launch(void* const* d_in, const int* in_sizes, int n_in,
                              void* d_out, int out_size) {
    const float* query    = (const float*)d_in[0];
    // d_in[1] = key: unused by the reference module
    const float* q_weight = (const float*)d_in[2];
    const float* q_bias   = (const float*)d_in[3];
    const float* weight   = (const float*)d_in[4];
    const float* pid      = (const float*)d_in[5];
    float* out = (float*)d_out;

    k_prep<<<16, 256>>>(q_weight, weight);
    k_bias<<<1, 128>>>(q_bias, weight);

    cudaFuncSetAttribute(k_proj, cudaFuncAttributeMaxDynamicSharedMemorySize, P_TOTAL);
    k_proj<<<MTOT / 128, 512, P_TOTAL>>>(query);

    cudaFuncSetAttribute(k_attn, cudaFuncAttributeMaxDynamicSharedMemorySize, S_TOT);
    dim3 g3(LL / 128, BB);   // (16, 8) = 128 CTAs, one wave
    k_attn<<<g3, 512, S_TOT>>>(pid, out);
}

// round 8
// speedup vs baseline: 1.1248x; 1.1248x over previous
#include <cuda_runtime.h>
#include <cuda_bf16.h>
#include <cstdint>
#include <cstddef>

#define BB 8
#define LL 2048
#define DM 1024
#define HH 120
#define HP 128
#define MTOT (BB*LL)
#define LOG2E 1.4426950408889634f

// ---------------------------------------------------------------------------
// Scratch (__device__ globals: allocation-free per harness rules)
// ---------------------------------------------------------------------------
__device__ __align__(16) float g_bc[HP];
__device__ __align__(16) float g_norm[MTOT];
__device__ __align__(16) __nv_bfloat16 g_WtH[HP * DM];
__device__ __align__(16) __nv_bfloat16 g_WtL[HP * DM];
__device__ __align__(16) __nv_bfloat16 g_uh[(size_t)MTOT * HP];
__device__ __align__(16) __nv_bfloat16 g_ul[(size_t)MTOT * HP];

// ---------------------------------------------------------------------------
// Helpers
// ---------------------------------------------------------------------------
__device__ __forceinline__ uint32_t smem_u32(const void* p) {
    uint32_t a;
    asm("{ .reg .u64 t; cvta.to.shared.u64 t, %1; cvt.u32.u64 %0, t; }" : "=r"(a) : "l"(p));
    return a;
}
__device__ __forceinline__ void ldsm4(uint32_t (&r)[4], uint32_t addr) {
    asm volatile("ldmatrix.sync.aligned.m8n8.x4.shared.b16 {%0,%1,%2,%3}, [%4];"
        : "=r"(r[0]), "=r"(r[1]), "=r"(r[2]), "=r"(r[3]) : "r"(addr));
}
__device__ __forceinline__ void hmma(float (&c)[4], const uint32_t (&a)[4],
                                     uint32_t b0, uint32_t b1) {
    asm volatile("mma.sync.aligned.m16n8k16.row.col.f32.bf16.bf16.f32 "
        "{%0,%1,%2,%3}, {%4,%5,%6,%7}, {%8,%9}, {%0,%1,%2,%3};"
        : "+f"(c[0]), "+f"(c[1]), "+f"(c[2]), "+f"(c[3])
        : "r"(a[0]), "r"(a[1]), "r"(a[2]), "r"(a[3]), "r"(b0), "r"(b1));
}
__device__ __forceinline__ void cpa16(uint32_t dst, const void* src) {
    asm volatile("cp.async.cg.shared.global [%0], [%1], 16;" :: "r"(dst), "l"(src));
}
#define CP_COMMIT() asm volatile("cp.async.commit_group;" ::: "memory")
#define CP_WAIT0()  asm volatile("cp.async.wait_group 0;" ::: "memory")

__device__ __forceinline__ float ex2(float x) {
    float r; asm("ex2.approx.ftz.f32 %0, %1;" : "=f"(r) : "f"(x)); return r;
}
__device__ __forceinline__ void split_store(__nv_bfloat16* H, __nv_bfloat16* L,
                                            size_t idx, float x, float y) {
    __nv_bfloat162 h = __floats2bfloat162_rn(x, y);
    float hx = __bfloat162float(h.x), hy = __bfloat162float(h.y);
    __nv_bfloat162 lo = __floats2bfloat162_rn(x - hx, y - hy);
    *(__nv_bfloat162*)(H + idx) = h;
    *(__nv_bfloat162*)(L + idx) = lo;
}

// TN mma over one k-chunk. A,B smem row-major [rows][k], stride STRB bytes.
// Warp tile 32(m) x 32(n). KS ksteps of k=16.
template<int STRB, int KS>
__device__ __forceinline__ void mma32(uint32_t aBase, uint32_t bBase,
                                      float (&acc)[2][4][4],
                                      int lid, int m0w, int n0) {
    uint32_t aA = aBase + (uint32_t)(m0w + (lid & 15)) * STRB + (uint32_t)((lid >> 4) * 16);
    uint32_t bA = bBase + (uint32_t)(n0 + (lid & 7) + ((lid >> 4) & 1) * 8) * STRB
                + (uint32_t)(((lid >> 3) & 1) * 16);
    #pragma unroll
    for (int ks = 0; ks < KS; ++ks) {
        uint32_t kb = (uint32_t)ks * 32;
        uint32_t afr[2][4];
        #pragma unroll
        for (int mt = 0; mt < 2; ++mt) ldsm4(afr[mt], aA + mt * 16 * STRB + kb);
        uint32_t bfr[2][4];
        #pragma unroll
        for (int g = 0; g < 2; ++g)    ldsm4(bfr[g], bA + g * 16 * STRB + kb);
        #pragma unroll
        for (int mt = 0; mt < 2; ++mt)
            #pragma unroll
            for (int nt = 0; nt < 4; ++nt)
                hmma(acc[mt][nt], afr[mt],
                     bfr[nt >> 1][(nt & 1) * 2], bfr[nt >> 1][(nt & 1) * 2 + 1]);
    }
}

// ---------------------------------------------------------------------------
// K1: Wc^T (bf16 hi/lo) + bias (block 0)
// ---------------------------------------------------------------------------
__global__ __launch_bounds__(256) void k_prep(const float* __restrict__ qw,
                                              const float* __restrict__ qb,
                                              const float* __restrict__ w) {
    __shared__ float Aq[8][64];
    __shared__ float Ww[8][128];
    int tid = threadIdx.x;
    int ty = tid >> 4, tx = tid & 15;
    int d0 = blockIdx.x * 64;

    float acc[4][8];
    #pragma unroll
    for (int r = 0; r < 4; ++r)
        #pragma unroll
        for (int c = 0; c < 8; ++c) acc[r][c] = 0.f;

    for (int kk = 0; kk < HH; kk += 8) {
        {
            int i = tid >> 5, j = (tid & 31) * 2;
            const float* s = &qw[(size_t)(kk + i) * DM + d0 + j];
            Aq[i][j] = s[0]; Aq[i][j + 1] = s[1];
        }
        {
            int i = tid >> 5, c = (tid & 31) * 4;
            #pragma unroll
            for (int q2 = 0; q2 < 4; ++q2) {
                int h = c + q2;
                Ww[i][h] = (h < HH) ? w[(size_t)(kk + i) * HH + h] : 0.f;
            }
        }
        __syncthreads();
        #pragma unroll
        for (int k = 0; k < 8; ++k) {
            float a[4], b[8];
            #pragma unroll
            for (int r = 0; r < 4; ++r) a[r] = Aq[k][ty * 4 + r];
            *(float4*)&b[0] = *(const float4*)&Ww[k][tx * 8];
            *(float4*)&b[4] = *(const float4*)&Ww[k][tx * 8 + 4];
            #pragma unroll
            for (int r = 0; r < 4; ++r)
                #pragma unroll
                for (int c = 0; c < 8; ++c) acc[r][c] += a[r] * b[c];
        }
        __syncthreads();
    }
    #pragma unroll
    for (int r = 0; r < 4; ++r)
        #pragma unroll
        for (int c = 0; c < 8; ++c) {
            int h = tx * 8 + c, d = d0 + ty * 4 + r;
            float v = acc[r][c];
            __nv_bfloat16 hb = __float2bfloat16(v);
            g_WtH[(size_t)h * DM + d] = hb;
            g_WtL[(size_t)h * DM + d] = __float2bfloat16(v - __bfloat162float(hb));
        }
    // fused bias (block 0)
    if (blockIdx.x == 0 && tid < 128) {
        int h = tid;
        float b = 0.f;
        if (h < HH) {
            #pragma unroll 4
            for (int p = 0; p < HH; ++p) b += qb[p] * w[p * HH + h];
        }
        g_bc[h] = b;
    }
}

// ---------------------------------------------------------------------------
// K2: u = query @ Wc + bc via bf16 split-3 HMMA. 512 thr, warp grid 4x4.
// ---------------------------------------------------------------------------
#define P_AH 0
#define P_AL 18432
#define P_BH 36864
#define P_BL 55296
#define P_BC 73728
#define P_RED 74240
#define P_TOTAL 76288
#define STR2 144

extern __shared__ char smem_dyn[];

__global__ __launch_bounds__(512, 1) void k_proj(const float* __restrict__ q) {
    char* sm = smem_dyn;
    uint32_t sb = smem_u32(sm);
    int tid = threadIdx.x;
    int wid = tid >> 5, lid = tid & 31;
    int m0w = (wid & 3) * 32;
    int nw = wid >> 2;
    int n0 = nw * 32;
    int m0g = blockIdx.x * 128;

    float* bc_s = (float*)(sm + P_BC);
    float* red = (float*)(sm + P_RED);
    if (tid < 128) bc_s[tid] = g_bc[tid];

    float acc[2][4][4];
    #pragma unroll
    for (int mt = 0; mt < 2; ++mt)
        #pragma unroll
        for (int nt = 0; nt < 4; ++nt)
            #pragma unroll
            for (int i = 0; i < 4; ++i) acc[mt][nt][i] = 0.f;

    float4 qr[4];
    #pragma unroll
    for (int l = 0; l < 4; ++l) {
        int i = tid + 512 * l, r = i >> 4, c4 = (i & 15) * 4;
        qr[l] = *(const float4*)&q[(size_t)(m0g + r) * DM + c4];
    }

    for (int kbi = 0; kbi < 16; ++kbi) {
        int kb = kbi * 64;
        #pragma unroll
        for (int l = 0; l < 2; ++l) {
            int i = tid + 512 * l, r = i >> 3, sg = i & 7;
            uint32_t doff = (uint32_t)r * STR2 + sg * 16;
            size_t soff = (size_t)r * (DM * 2) + (size_t)kb * 2 + sg * 16;
            cpa16(sb + P_BH + doff, (const char*)g_WtH + soff);
            cpa16(sb + P_BL + doff, (const char*)g_WtL + soff);
        }
        CP_COMMIT();
        #pragma unroll
        for (int l = 0; l < 4; ++l) {
            int i = tid + 512 * l, r = i >> 4, c4 = (i & 15) * 4;
            float4 v = qr[l];
            __nv_bfloat162 h01 = __floats2bfloat162_rn(v.x, v.y);
            __nv_bfloat162 h23 = __floats2bfloat162_rn(v.z, v.w);
            __nv_bfloat162 l01 = __floats2bfloat162_rn(v.x - __bfloat162float(h01.x),
                                                       v.y - __bfloat162float(h01.y));
            __nv_bfloat162 l23 = __floats2bfloat162_rn(v.z - __bfloat162float(h23.x),
                                                       v.w - __bfloat162float(h23.y));
            char* d = sm + P_AH + r * STR2 + c4 * 2;
            ((__nv_bfloat162*)d)[0] = h01; ((__nv_bfloat162*)d)[1] = h23;
            char* d2 = sm + P_AL + r * STR2 + c4 * 2;
            ((__nv_bfloat162*)d2)[0] = l01; ((__nv_bfloat162*)d2)[1] = l23;
        }
        if (kbi < 15) {
            #pragma unroll
            for (int l = 0; l < 4; ++l) {
                int i = tid + 512 * l, r = i >> 4, c4 = (i & 15) * 4;
                qr[l] = *(const float4*)&q[(size_t)(m0g + r) * DM + kb + 64 + c4];
            }
        }
        CP_WAIT0();
        __syncthreads();
        mma32<STR2, 4>(sb + P_AH, sb + P_BH, acc, lid, m0w, n0);
        mma32<STR2, 4>(sb + P_AH, sb + P_BL, acc, lid, m0w, n0);
        mma32<STR2, 4>(sb + P_AL, sb + P_BH, acc, lid, m0w, n0);
        __syncthreads();
    }

    float sums[2][2] = {{0.f, 0.f}, {0.f, 0.f}};
    #pragma unroll
    for (int mt = 0; mt < 2; ++mt)
        #pragma unroll
        for (int nt = 0; nt < 4; ++nt) {
            int col = n0 + nt * 8 + (lid & 3) * 2;
            float b0 = bc_s[col], b1 = bc_s[col + 1];
            int r1 = m0w + mt * 16 + (lid >> 2);
            float u00 = acc[mt][nt][0] + b0, u01 = acc[mt][nt][1] + b1;
            float u10 = acc[mt][nt][2] + b0, u11 = acc[mt][nt][3] + b1;
            sums[mt][0] += u00 * u00 + u01 * u01;
            sums[mt][1] += u10 * u10 + u11 * u11;
            split_store(g_uh, g_ul, (size_t)(m0g + r1) * HP + col, u00, u01);
            split_store(g_uh, g_ul, (size_t)(m0g + r1 + 8) * HP + col, u10, u11);
        }
    #pragma unroll
    for (int mt = 0; mt < 2; ++mt)
        #pragma unroll
        for (int hf = 0; hf < 2; ++hf) {
            float s = sums[mt][hf];
            s += __shfl_xor_sync(0xFFFFFFFF, s, 1);
            s += __shfl_xor_sync(0xFFFFFFFF, s, 2);
            if ((lid & 3) == 0)
                red[nw * 128 + m0w + mt * 16 + (lid >> 2) + hf * 8] = s;
        }
    __syncthreads();
    if (tid < 128)
        g_norm[m0g + tid] = (red[tid] + red[128 + tid]) + (red[256 + tid] + red[384 + tid]);
}

// ---------------------------------------------------------------------------
// K3: scores. 512 thr, 4x4 warp grid. Direct fragment-layout stores, per-thread
// row partials, ONE sync per j-tile.
// ---------------------------------------------------------------------------
#define A_H    0
#define A_L    34816
#define B0_H   69632
#define B1_H   139264
#define S_NJ   208896
#define S_RED  217088
#define S_RINV 219136
#define S_TOT  219648
#define STR3   272
#define BTILE  34816

__device__ __forceinline__ void k3_cp_tile(uint32_t dstH, uint32_t dstL,
                                           int row0, int tid) {
    #pragma unroll
    for (int l = 0; l < 4; ++l) {
        int i = tid + 512 * l, r = i >> 4, c = i & 15;
        uint32_t doff = (uint32_t)r * STR3 + c * 16;
        size_t soff = (size_t)(row0 + r) * (HP * 2) + c * 16;
        cpa16(dstH + doff, (const char*)g_uh + soff);
        cpa16(dstL + doff, (const char*)g_ul + soff);
    }
}

__global__ __launch_bounds__(512, 1) void k_attn(const float* __restrict__ pid,
                                                 float* __restrict__ out) {
    char* sm = smem_dyn;
    uint32_t sb = smem_u32(sm);
    int tid = threadIdx.x;
    int wid = tid >> 5, lid = tid & 31;
    int m0w = (wid & 3) * 32;
    int n0 = (wid >> 2) * 32;

    int b = blockIdx.y;
    int stripe = blockIdx.x;
    int i0 = b * LL + stripe * 128;

    float scale = pid[0] * pid[0];
    float c1 = -0.5f * scale * LOG2E;
    float m2c1 = -2.f * c1;

    float* nj_s = (float*)(sm + S_NJ);    // c1-scaled norms, 2048 floats
    float* red = (float*)(sm + S_RED);    // 4 x 128
    float* rinv_s = (float*)(sm + S_RINV);

    {   // nj scaled by c1
        const float4* njs = (const float4*)&g_norm[b * LL];
        float4 v = njs[tid];
        v.x *= c1; v.y *= c1; v.z *= c1; v.w *= c1;
        ((float4*)nj_s)[tid] = v;
    }
    // per-thread c1*ni for the 4 owned rows: row = m0w + mt*16 + hf*8 + (lid>>2)
    float nir[4];
    #pragma unroll
    for (int k = 0; k < 4; ++k)
        nir[k] = c1 * g_norm[i0 + m0w + (k >> 1) * 16 + (k & 1) * 8 + (lid >> 2)];

    k3_cp_tile(sb + A_H, sb + A_L, i0, tid);
    k3_cp_tile(sb + B0_H, sb + B0_H + BTILE, b * LL, tid);
    CP_COMMIT();
    CP_WAIT0();
    __syncthreads();

    float rs[4] = {0.f, 0.f, 0.f, 0.f};

    // per-thread output row pointers (4 rows)
    float* orow[4];
    #pragma unroll
    for (int k = 0; k < 4; ++k)
        orow[k] = out + (size_t)(i0 + m0w + (k >> 1) * 16 + (k & 1) * 8 + (lid >> 2)) * LL;

    for (int jt = 0; jt < 16; ++jt) {
        int buf = jt & 1;
        uint32_t bH = sb + (buf ? B1_H : B0_H);
        uint32_t bL = bH + BTILE;
        if (jt < 15) {
            uint32_t nH = sb + ((buf ^ 1) ? B1_H : B0_H);
            k3_cp_tile(nH, nH + BTILE, b * LL + (jt + 1) * 128, tid);
            CP_COMMIT();
        }

        float acc[2][4][4];
        #pragma unroll
        for (int mt = 0; mt < 2; ++mt)
            #pragma unroll
            for (int nt = 0; nt < 4; ++nt)
                #pragma unroll
                for (int i = 0; i < 4; ++i) acc[mt][nt][i] = 0.f;

        mma32<STR3, 8>(sb + A_H, bH, acc, lid, m0w, n0);
        mma32<STR3, 8>(sb + A_H, bL, acc, lid, m0w, n0);
        mma32<STR3, 8>(sb + A_L, bH, acc, lid, m0w, n0);

        // epilogue: direct from fragments. col pair per (nt): 2 consecutive cols.
        #pragma unroll
        for (int nt = 0; nt < 4; ++nt) {
            int colL = n0 + nt * 8 + (lid & 3) * 2;          // 0..127
            int col = jt * 128 + colL;                        // global j
            float2 cnj = *(float2*)&nj_s[col];
            #pragma unroll
            for (int mt = 0; mt < 2; ++mt) {
                float e00 = ex2(LOG2E * ex2(fmaf(m2c1, acc[mt][nt][0], nir[mt * 2] + cnj.x)));
                float e01 = ex2(LOG2E * ex2(fmaf(m2c1, acc[mt][nt][1], nir[mt * 2] + cnj.y)));
                float e10 = ex2(LOG2E * ex2(fmaf(m2c1, acc[mt][nt][2], nir[mt * 2 + 1] + cnj.x)));
                float e11 = ex2(LOG2E * ex2(fmaf(m2c1, acc[mt][nt][3], nir[mt * 2 + 1] + cnj.y)));
                rs[mt * 2] += e00 + e01;
                rs[mt * 2 + 1] += e10 + e11;
                *(float2*)&orow[mt * 2][col] = make_float2(e00, e01);
                *(float2*)&orow[mt * 2 + 1][col] = make_float2(e10, e11);
            }
        }
        CP_WAIT0();
        __syncthreads();   // guards: all warps' MMA reads done before next cp.async overwrite
    }

    // one-time row-sum reduction: quad lanes, then 4 n-warps via smem
    #pragma unroll
    for (int k = 0; k < 4; ++k) {
        float s = rs[k];
        s += __shfl_xor_sync(0xFFFFFFFF, s, 1);
        s += __shfl_xor_sync(0xFFFFFFFF, s, 2);
        if ((lid & 3) == 0)
            red[(wid >> 2) * 128 + m0w + (k >> 1) * 16 + (k & 1) * 8 + (lid >> 2)] = s;
    }
    __syncthreads();
    if (tid < 128)
        rinv_s[tid] = 1.0f / ((red[tid] + red[128 + tid]) + (red[256 + tid] + red[384 + tid]));
    __syncthreads();

    // normalize pass (coalesced; 16 warps x 8 rows)
    #pragma unroll 1
    for (int rr = 0; rr < 8; ++rr) {
        int row = wid * 8 + rr;
        float sc = rinv_s[row];
        float* rp = &out[(size_t)(i0 + row) * LL];
        #pragma unroll 4
        for (int seg = 0; seg < 16; ++seg) {
            int idx = seg * 128 + lid * 4;
            float4 v = *(float4*)&rp[idx];
            v.x *= sc; v.y *= sc; v.z *= sc; v.w *= sc;
            *(float4*)&rp[idx] = v;
        }
    }
}

// ---------------------------------------------------------------------------
extern "C" void kernel_launch(void* const* d_in, const int* in_sizes, int n_in,
                              void* d_out, int out_size) {
    const float* query    = (const float*)d_in[0];
    // d_in[1] = key: unused by the reference module
    const float* q_weight = (const float*)d_in[2];
    const float* q_bias   = (const float*)d_in[3];
    const float* weight   = (const float*)d_in[4];
    const float* pid      = (const float*)d_in[5];
    float* out = (float*)d_out;

    k_prep<<<16, 256>>>(q_weight, q_bias, weight);

    cudaFuncSetAttribute(k_proj, cudaFuncAttributeMaxDynamicSharedMemorySize, P_TOTAL);
    k_proj<<<MTOT / 128, 512, P_TOTAL>>>(query);

    cudaFuncSetAttribute(k_attn, cudaFuncAttributeMaxDynamicSharedMemorySize, S_TOT);
    dim3 g3(LL / 128, BB);   // (16, 8) = 128 CTAs, one wave
    k_attn<<<g3, 512, S_TOT>>>(pid, out);
}

// round 9
// speedup vs baseline: 1.2111x; 1.0767x over previous
#include <cuda_runtime.h>
#include <cuda_bf16.h>
#include <cstdint>
#include <cstddef>

#define BB 8
#define LL 2048
#define DM 1024
#define HH 120
#define HP 128
#define MTOT (BB*LL)
#define LOG2E 1.4426950408889634f

// ---------------------------------------------------------------------------
// Scratch (__device__ globals: allocation-free per harness rules)
// ---------------------------------------------------------------------------
__device__ __align__(16) float g_bc[HP];
__device__ __align__(16) float g_norm[MTOT];
__device__ __align__(16) __nv_bfloat16 g_WtH[HP * DM];
__device__ __align__(16) __nv_bfloat16 g_WtL[HP * DM];
__device__ __align__(16) __nv_bfloat16 g_uh[(size_t)MTOT * HP];
__device__ __align__(16) __nv_bfloat16 g_ul[(size_t)MTOT * HP];

// ---------------------------------------------------------------------------
// Helpers
// ---------------------------------------------------------------------------
__device__ __forceinline__ uint32_t smem_u32(const void* p) {
    uint32_t a;
    asm("{ .reg .u64 t; cvta.to.shared.u64 t, %1; cvt.u32.u64 %0, t; }" : "=r"(a) : "l"(p));
    return a;
}
__device__ __forceinline__ void ldsm4(uint32_t (&r)[4], uint32_t addr) {
    asm volatile("ldmatrix.sync.aligned.m8n8.x4.shared.b16 {%0,%1,%2,%3}, [%4];"
        : "=r"(r[0]), "=r"(r[1]), "=r"(r[2]), "=r"(r[3]) : "r"(addr));
}
__device__ __forceinline__ void hmma(float (&c)[4], const uint32_t (&a)[4],
                                     uint32_t b0, uint32_t b1) {
    asm volatile("mma.sync.aligned.m16n8k16.row.col.f32.bf16.bf16.f32 "
        "{%0,%1,%2,%3}, {%4,%5,%6,%7}, {%8,%9}, {%0,%1,%2,%3};"
        : "+f"(c[0]), "+f"(c[1]), "+f"(c[2]), "+f"(c[3])
        : "r"(a[0]), "r"(a[1]), "r"(a[2]), "r"(a[3]), "r"(b0), "r"(b1));
}
__device__ __forceinline__ void cpa16(uint32_t dst, const void* src) {
    asm volatile("cp.async.cg.shared.global [%0], [%1], 16;" :: "r"(dst), "l"(src));
}
#define CP_COMMIT() asm volatile("cp.async.commit_group;" ::: "memory")
#define CP_WAIT0()  asm volatile("cp.async.wait_group 0;" ::: "memory")

__device__ __forceinline__ float ex2(float x) {
    float r; asm("ex2.approx.ftz.f32 %0, %1;" : "=f"(r) : "f"(x)); return r;
}
// exp(s) for s in [0, ~1]: degree-8 Taylor (Horner), rel err < 1e-5
__device__ __forceinline__ float exp8(float s) {
    float e = fmaf(s, 2.4801587e-5f, 1.9841270e-4f);
    e = fmaf(e, s, 1.3888889e-3f);
    e = fmaf(e, s, 8.3333333e-3f);
    e = fmaf(e, s, 4.1666667e-2f);
    e = fmaf(e, s, 1.6666667e-1f);
    e = fmaf(e, s, 0.5f);
    e = fmaf(e, s, 1.0f);
    e = fmaf(e, s, 1.0f);
    return e;
}
__device__ __forceinline__ void split_store(__nv_bfloat16* H, __nv_bfloat16* L,
                                            size_t idx, float x, float y) {
    __nv_bfloat162 h = __floats2bfloat162_rn(x, y);
    float hx = __bfloat162float(h.x), hy = __bfloat162float(h.y);
    __nv_bfloat162 lo = __floats2bfloat162_rn(x - hx, y - hy);
    *(__nv_bfloat162*)(H + idx) = h;
    *(__nv_bfloat162*)(L + idx) = lo;
}

// TN mma over one k-chunk. A,B smem row-major [rows][k], stride STRB bytes.
// Warp tile 32(m) x 32(n). KS ksteps of k=16.
template<int STRB, int KS>
__device__ __forceinline__ void mma32(uint32_t aBase, uint32_t bBase,
                                      float (&acc)[2][4][4],
                                      int lid, int m0w, int n0) {
    uint32_t aA = aBase + (uint32_t)(m0w + (lid & 15)) * STRB + (uint32_t)((lid >> 4) * 16);
    uint32_t bA = bBase + (uint32_t)(n0 + (lid & 7) + ((lid >> 4) & 1) * 8) * STRB
                + (uint32_t)(((lid >> 3) & 1) * 16);
    #pragma unroll
    for (int ks = 0; ks < KS; ++ks) {
        uint32_t kb = (uint32_t)ks * 32;
        uint32_t afr[2][4];
        #pragma unroll
        for (int mt = 0; mt < 2; ++mt) ldsm4(afr[mt], aA + mt * 16 * STRB + kb);
        uint32_t bfr[2][4];
        #pragma unroll
        for (int g = 0; g < 2; ++g)    ldsm4(bfr[g], bA + g * 16 * STRB + kb);
        #pragma unroll
        for (int mt = 0; mt < 2; ++mt)
            #pragma unroll
            for (int nt = 0; nt < 4; ++nt)
                hmma(acc[mt][nt], afr[mt],
                     bfr[nt >> 1][(nt & 1) * 2], bfr[nt >> 1][(nt & 1) * 2 + 1]);
    }
}

extern __shared__ char smem_dyn[];

// ---------------------------------------------------------------------------
// K1: Wc^T (bf16 hi/lo) + bias. One-shot: 128 CTAs x 256 thr, 8 d-cols each.
// ws[h][p] (stride 121, conflict-free), Aq[p][dd] broadcast.
// ---------------------------------------------------------------------------
#define PREP_SMEM (128 * 121 * 4)

__global__ __launch_bounds__(256) void k_prep(const float* __restrict__ qw,
                                              const float* __restrict__ qb,
                                              const float* __restrict__ w) {
    float* ws = (float*)smem_dyn;          // [128][121] (rows >=120 unused)
    __shared__ float Aq[120][8];
    int tid = threadIdx.x;
    int h = tid & 127, dg = tid >> 7;      // dg: 0/1 -> which 4 d's
    int d0 = blockIdx.x * 8;

    for (int i = tid; i < HH * HH; i += 256) {
        int p = i / HH, hh = i - p * HH;
        ws[hh * 121 + p] = w[i];
    }
    for (int i = tid; i < HH * 8; i += 256) {
        int p = i >> 3, dd = i & 7;
        Aq[p][dd] = qw[(size_t)p * DM + d0 + dd];
    }
    __syncthreads();

    float acc[4] = {0.f, 0.f, 0.f, 0.f};
    if (h < HH) {
        #pragma unroll 4
        for (int p = 0; p < HH; ++p) {
            float wv = ws[h * 121 + p];
            float4 aq = *(float4*)&Aq[p][dg * 4];
            acc[0] = fmaf(aq.x, wv, acc[0]);
            acc[1] = fmaf(aq.y, wv, acc[1]);
            acc[2] = fmaf(aq.z, wv, acc[2]);
            acc[3] = fmaf(aq.w, wv, acc[3]);
        }
    }
    #pragma unroll
    for (int dd = 0; dd < 4; ++dd) {
        int d = d0 + dg * 4 + dd;
        float v = acc[dd];
        __nv_bfloat16 hb = __float2bfloat16(v);
        g_WtH[(size_t)h * DM + d] = hb;
        g_WtL[(size_t)h * DM + d] = __float2bfloat16(v - __bfloat162float(hb));
    }
    if (blockIdx.x == 0 && tid < 128) {
        float b = 0.f;
        if (tid < HH) {
            #pragma unroll 4
            for (int p = 0; p < HH; ++p) b = fmaf(qb[p], ws[tid * 121 + p], b);
        }
        g_bc[tid] = b;
    }
}

// ---------------------------------------------------------------------------
// K2: u = query @ Wc + bc via bf16 split-3 HMMA, software-pipelined (double-
// buffered A/B chunks, one sync per iter). 512 thr, warp grid 4x4.
// ---------------------------------------------------------------------------
#define P_AH(b) ((b) * 73728 + 0)
#define P_AL(b) ((b) * 73728 + 18432)
#define P_BH(b) ((b) * 73728 + 36864)
#define P_BL(b) ((b) * 73728 + 55296)
#define P_BC 147456
#define P_RED 147968
#define P_TOTAL 150016
#define STR2 144

__device__ __forceinline__ void k2_cpB(uint32_t sb, int buf, int kb, int tid) {
    #pragma unroll
    for (int l = 0; l < 2; ++l) {
        int i = tid + 512 * l, r = i >> 3, sg = i & 7;
        uint32_t doff = (uint32_t)r * STR2 + sg * 16;
        size_t soff = (size_t)r * (DM * 2) + (size_t)kb * 2 + sg * 16;
        cpa16(sb + P_BH(buf) + doff, (const char*)g_WtH + soff);
        cpa16(sb + P_BL(buf) + doff, (const char*)g_WtL + soff);
    }
}
__device__ __forceinline__ void k2_convA(char* sm, int buf, const float4* qr, int tid) {
    #pragma unroll
    for (int l = 0; l < 4; ++l) {
        int i = tid + 512 * l, r = i >> 4, c4 = (i & 15) * 4;
        float4 v = qr[l];
        __nv_bfloat162 h01 = __floats2bfloat162_rn(v.x, v.y);
        __nv_bfloat162 h23 = __floats2bfloat162_rn(v.z, v.w);
        __nv_bfloat162 l01 = __floats2bfloat162_rn(v.x - __bfloat162float(h01.x),
                                                   v.y - __bfloat162float(h01.y));
        __nv_bfloat162 l23 = __floats2bfloat162_rn(v.z - __bfloat162float(h23.x),
                                                   v.w - __bfloat162float(h23.y));
        char* d = sm + P_AH(buf) + r * STR2 + c4 * 2;
        ((__nv_bfloat162*)d)[0] = h01; ((__nv_bfloat162*)d)[1] = h23;
        char* d2 = sm + P_AL(buf) + r * STR2 + c4 * 2;
        ((__nv_bfloat162*)d2)[0] = l01; ((__nv_bfloat162*)d2)[1] = l23;
    }
}

__global__ __launch_bounds__(512, 1) void k_proj(const float* __restrict__ q) {
    char* sm = smem_dyn;
    uint32_t sb = smem_u32(sm);
    int tid = threadIdx.x;
    int wid = tid >> 5, lid = tid & 31;
    int m0w = (wid & 3) * 32;
    int nw = wid >> 2;
    int n0 = nw * 32;
    int m0g = blockIdx.x * 128;

    float* bc_s = (float*)(sm + P_BC);
    float* red = (float*)(sm + P_RED);
    if (tid < 128) bc_s[tid] = g_bc[tid];

    float acc[2][4][4];
    #pragma unroll
    for (int mt = 0; mt < 2; ++mt)
        #pragma unroll
        for (int nt = 0; nt < 4; ++nt)
            #pragma unroll
            for (int i = 0; i < 4; ++i) acc[mt][nt][i] = 0.f;

    float4 qr[4];
    #pragma unroll
    for (int l = 0; l < 4; ++l) {
        int i = tid + 512 * l, r = i >> 4, c4 = (i & 15) * 4;
        qr[l] = *(const float4*)&q[(size_t)(m0g + r) * DM + c4];
    }
    // preamble: chunk 0 into buf0, prefetch chunk1 regs
    k2_cpB(sb, 0, 0, tid);
    CP_COMMIT();
    k2_convA(sm, 0, qr, tid);
    #pragma unroll
    for (int l = 0; l < 4; ++l) {
        int i = tid + 512 * l, r = i >> 4, c4 = (i & 15) * 4;
        qr[l] = *(const float4*)&q[(size_t)(m0g + r) * DM + 64 + c4];
    }
    CP_WAIT0();
    __syncthreads();

    for (int kbi = 0; kbi < 16; ++kbi) {
        int buf = kbi & 1;
        if (kbi < 15) {
            k2_cpB(sb, buf ^ 1, (kbi + 1) * 64, tid);
            CP_COMMIT();
            k2_convA(sm, buf ^ 1, qr, tid);
            if (kbi < 14) {
                #pragma unroll
                for (int l = 0; l < 4; ++l) {
                    int i = tid + 512 * l, r = i >> 4, c4 = (i & 15) * 4;
                    qr[l] = *(const float4*)&q[(size_t)(m0g + r) * DM + (kbi + 2) * 64 + c4];
                }
            }
        }
        mma32<STR2, 4>(sb + P_AH(buf), sb + P_BH(buf), acc, lid, m0w, n0);
        mma32<STR2, 4>(sb + P_AH(buf), sb + P_BL(buf), acc, lid, m0w, n0);
        mma32<STR2, 4>(sb + P_AL(buf), sb + P_BH(buf), acc, lid, m0w, n0);
        if (kbi < 15) CP_WAIT0();
        __syncthreads();
    }

    float sums[2][2] = {{0.f, 0.f}, {0.f, 0.f}};
    #pragma unroll
    for (int mt = 0; mt < 2; ++mt)
        #pragma unroll
        for (int nt = 0; nt < 4; ++nt) {
            int col = n0 + nt * 8 + (lid & 3) * 2;
            float b0 = bc_s[col], b1 = bc_s[col + 1];
            int r1 = m0w + mt * 16 + (lid >> 2);
            float u00 = acc[mt][nt][0] + b0, u01 = acc[mt][nt][1] + b1;
            float u10 = acc[mt][nt][2] + b0, u11 = acc[mt][nt][3] + b1;
            sums[mt][0] += u00 * u00 + u01 * u01;
            sums[mt][1] += u10 * u10 + u11 * u11;
            split_store(g_uh, g_ul, (size_t)(m0g + r1) * HP + col, u00, u01);
            split_store(g_uh, g_ul, (size_t)(m0g + r1 + 8) * HP + col, u10, u11);
        }
    #pragma unroll
    for (int mt = 0; mt < 2; ++mt)
        #pragma unroll
        for (int hf = 0; hf < 2; ++hf) {
            float s = sums[mt][hf];
            s += __shfl_xor_sync(0xFFFFFFFF, s, 1);
            s += __shfl_xor_sync(0xFFFFFFFF, s, 2);
            if ((lid & 3) == 0)
                red[nw * 128 + m0w + mt * 16 + (lid >> 2) + hf * 8] = s;
        }
    __syncthreads();
    if (tid < 128)
        g_norm[m0g + tid] = (red[tid] + red[128 + tid]) + (red[256 + tid] + red[384 + tid]);
}

// ---------------------------------------------------------------------------
// K3: scores. 512 thr, 4x4 warp grid. Direct fragment-layout stores, per-thread
// row partials, ONE sync per j-tile. Poly exp on FMA pipe.
// ---------------------------------------------------------------------------
#define A_H    0
#define A_L    34816
#define B0_H   69632
#define B1_H   139264
#define S_NJ   208896
#define S_RED  217088
#define S_RINV 219136
#define S_TOT  219648
#define STR3   272
#define BTILE  34816

__device__ __forceinline__ void k3_cp_tile(uint32_t dstH, uint32_t dstL,
                                           int row0, int tid) {
    #pragma unroll
    for (int l = 0; l < 4; ++l) {
        int i = tid + 512 * l, r = i >> 4, c = i & 15;
        uint32_t doff = (uint32_t)r * STR3 + c * 16;
        size_t soff = (size_t)(row0 + r) * (HP * 2) + c * 16;
        cpa16(dstH + doff, (const char*)g_uh + soff);
        cpa16(dstL + doff, (const char*)g_ul + soff);
    }
}

__global__ __launch_bounds__(512, 1) void k_attn(const float* __restrict__ pid,
                                                 float* __restrict__ out) {
    char* sm = smem_dyn;
    uint32_t sb = smem_u32(sm);
    int tid = threadIdx.x;
    int wid = tid >> 5, lid = tid & 31;
    int m0w = (wid & 3) * 32;
    int n0 = (wid >> 2) * 32;

    int b = blockIdx.y;
    int stripe = blockIdx.x;
    int i0 = b * LL + stripe * 128;

    float scale = pid[0] * pid[0];
    float c1 = -0.5f * scale * LOG2E;
    float m2c1 = -2.f * c1;

    float* nj_s = (float*)(sm + S_NJ);    // c1-scaled norms, 2048 floats
    float* red = (float*)(sm + S_RED);    // 4 x 128
    float* rinv_s = (float*)(sm + S_RINV);

    {
        const float4* njs = (const float4*)&g_norm[b * LL];
        float4 v = njs[tid];
        v.x *= c1; v.y *= c1; v.z *= c1; v.w *= c1;
        ((float4*)nj_s)[tid] = v;
    }
    float nir[4];
    #pragma unroll
    for (int k = 0; k < 4; ++k)
        nir[k] = c1 * g_norm[i0 + m0w + (k >> 1) * 16 + (k & 1) * 8 + (lid >> 2)];

    k3_cp_tile(sb + A_H, sb + A_L, i0, tid);
    k3_cp_tile(sb + B0_H, sb + B0_H + BTILE, b * LL, tid);
    CP_COMMIT();
    CP_WAIT0();
    __syncthreads();

    float rs[4] = {0.f, 0.f, 0.f, 0.f};

    float* orow[4];
    #pragma unroll
    for (int k = 0; k < 4; ++k)
        orow[k] = out + (size_t)(i0 + m0w + (k >> 1) * 16 + (k & 1) * 8 + (lid >> 2)) * LL;

    for (int jt = 0; jt < 16; ++jt) {
        int buf = jt & 1;
        uint32_t bH = sb + (buf ? B1_H : B0_H);
        uint32_t bL = bH + BTILE;
        if (jt < 15) {
            uint32_t nH = sb + ((buf ^ 1) ? B1_H : B0_H);
            k3_cp_tile(nH, nH + BTILE, b * LL + (jt + 1) * 128, tid);
            CP_COMMIT();
        }

        float acc[2][4][4];
        #pragma unroll
        for (int mt = 0; mt < 2; ++mt)
            #pragma unroll
            for (int nt = 0; nt < 4; ++nt)
                #pragma unroll
                for (int i = 0; i < 4; ++i) acc[mt][nt][i] = 0.f;

        mma32<STR3, 8>(sb + A_H, bH, acc, lid, m0w, n0);
        mma32<STR3, 8>(sb + A_H, bL, acc, lid, m0w, n0);
        mma32<STR3, 8>(sb + A_L, bH, acc, lid, m0w, n0);

        #pragma unroll
        for (int nt = 0; nt < 4; ++nt) {
            int colL = n0 + nt * 8 + (lid & 3) * 2;
            int col = jt * 128 + colL;
            float2 cnj = *(float2*)&nj_s[col];
            #pragma unroll
            for (int mt = 0; mt < 2; ++mt) {
                float e00 = exp8(ex2(fmaf(m2c1, acc[mt][nt][0], nir[mt * 2] + cnj.x)));
                float e01 = exp8(ex2(fmaf(m2c1, acc[mt][nt][1], nir[mt * 2] + cnj.y)));
                float e10 = exp8(ex2(fmaf(m2c1, acc[mt][nt][2], nir[mt * 2 + 1] + cnj.x)));
                float e11 = exp8(ex2(fmaf(m2c1, acc[mt][nt][3], nir[mt * 2 + 1] + cnj.y)));
                rs[mt * 2] += e00 + e01;
                rs[mt * 2 + 1] += e10 + e11;
                *(float2*)&orow[mt * 2][col] = make_float2(e00, e01);
                *(float2*)&orow[mt * 2 + 1][col] = make_float2(e10, e11);
            }
        }
        CP_WAIT0();
        __syncthreads();
    }

    #pragma unroll
    for (int k = 0; k < 4; ++k) {
        float s = rs[k];
        s += __shfl_xor_sync(0xFFFFFFFF, s, 1);
        s += __shfl_xor_sync(0xFFFFFFFF, s, 2);
        if ((lid & 3) == 0)
            red[(wid >> 2) * 128 + m0w + (k >> 1) * 16 + (k & 1) * 8 + (lid >> 2)] = s;
    }
    __syncthreads();
    if (tid < 128)
        rinv_s[tid] = 1.0f / ((red[tid] + red[128 + tid]) + (red[256 + tid] + red[384 + tid]));
    __syncthreads();

    #pragma unroll 1
    for (int rr = 0; rr < 8; ++rr) {
        int row = wid * 8 + rr;
        float sc = rinv_s[row];
        float* rp = &out[(size_t)(i0 + row) * LL];
        #pragma unroll 4
        for (int seg = 0; seg < 16; ++seg) {
            int idx = seg * 128 + lid * 4;
            float4 v = *(float4*)&rp[idx];
            v.x *= sc; v.y *= sc; v.z *= sc; v.w *= sc;
            *(float4*)&rp[idx] = v;
        }
    }
}

// ---------------------------------------------------------------------------
extern "C" void kernel_launch(void* const* d_in, const int* in_sizes, int n_in,
                              void* d_out, int out_size) {
    const float* query    = (const float*)d_in[0];
    // d_in[1] = key: unused by the reference module
    const float* q_weight = (const float*)d_in[2];
    const float* q_bias   = (const float*)d_in[3];
    const float* weight   = (const float*)d_in[4];
    const float* pid      = (const float*)d_in[5];
    float* out = (float*)d_out;

    cudaFuncSetAttribute(k_prep, cudaFuncAttributeMaxDynamicSharedMemorySize, PREP_SMEM);
    k_prep<<<DM / 8, 256, PREP_SMEM>>>(q_weight, q_bias, weight);

    cudaFuncSetAttribute(k_proj, cudaFuncAttributeMaxDynamicSharedMemorySize, P_TOTAL);
    k_proj<<<MTOT / 128, 512, P_TOTAL>>>(query);

    cudaFuncSetAttribute(k_attn, cudaFuncAttributeMaxDynamicSharedMemorySize, S_TOT);
    dim3 g3(LL / 128, BB);   // (16, 8) = 128 CTAs, one wave
    k_attn<<<g3, 512, S_TOT>>>(pid, out);
}